// round 14
// baseline (speedup 1.0000x reference)
#include <cuda_runtime.h>
#include <cuda_bf16.h>
#include <cstdint>

#define BB 16
#define NN 512
#define FF 625
#define FH 937
#define FFP 640      // F padded (mult of 128)
#define FHPN 1024    // Fh padded for N-dim (mult of 128)
#define FHPK 944     // Fh padded for K-dim (mult of 16)

typedef __nv_bfloat16 bf16;

// ---------------- scratch (no allocs allowed -> device globals) -------------
__device__ bf16  g_A[(size_t)BB * NN * NN];   // adjacency 0/1 in SORTED space
__device__ float g_deg[(size_t)BB * NN];      // row degree (exact integer in fp32)
__device__ float g_atts[(size_t)BB * NN];     // sorted att values
__device__ int   g_perm[(size_t)BB * NN];     // perm[i] = original index of i-th smallest

__device__ bf16 g_Xh[(size_t)BB * NN * FFP],  g_Xl[(size_t)BB * NN * FFP];
__device__ bf16 g_Th[(size_t)BB * NN * FFP],  g_Tl[(size_t)BB * NN * FFP];
__device__ bf16 g_hh[(size_t)BB * NN * FHPN], g_hl[(size_t)BB * NN * FHPN];
__device__ bf16 g_T2h[(size_t)BB * NN * FHPN], g_T2l[(size_t)BB * NN * FHPN];
__device__ bf16 g_W1h[2ul * FFP * FHPN],  g_W1l[2ul * FFP * FHPN];
__device__ bf16 g_W2h[2ul * FHPK * FFP],  g_W2l[2ul * FHPK * FFP];
__device__ float g_b1p[FHPN], g_b2p[FFP];

// ---------------------------------------------------------------------------
// Kernel 0: bitonic sort of att per batch; also zeroes deg.
// ---------------------------------------------------------------------------
__global__ __launch_bounds__(512) void sort_kernel(const float* __restrict__ att)
{
    __shared__ float key[NN];
    __shared__ int   idx[NN];
    const int b = blockIdx.x;
    const int t = threadIdx.x;

    g_deg[(size_t)b * NN + t] = 0.f;

    key[t] = att[(size_t)b * NN + t];
    idx[t] = t;
    __syncthreads();

    for (int sz = 2; sz <= NN; sz <<= 1) {
        for (int st = sz >> 1; st > 0; st >>= 1) {
            const int p = t ^ st;
            if (p > t) {
                const bool up = ((t & sz) == 0);
                const float a = key[t], c = key[p];
                if (up ? (a > c) : (a < c)) {
                    key[t] = c; key[p] = a;
                    const int ia = idx[t]; idx[t] = idx[p]; idx[p] = ia;
                }
            }
            __syncthreads();
        }
    }
    g_atts[(size_t)b * NN + t] = key[t];
    g_perm[(size_t)b * NN + t] = idx[t];
}

// ---------------------------------------------------------------------------
// Kernel 1: thresholded adjacency in sorted space (band prune + symmetry),
// with exact row-degree accumulation via float atomicAdd.
// ---------------------------------------------------------------------------
__global__ __launch_bounds__(256) void adj_kernel(
    const float* __restrict__ X, bf16* __restrict__ A, float* __restrict__ deg)
{
    const int b  = blockIdx.z;
    const int bi = blockIdx.y;
    const int bj = blockIdx.x;
    if (bj < bi) return;
    const int i0 = bi * 64;
    const int j0 = bj * 64;
    const float* as = g_atts + (size_t)b * NN;
    const int* permB = g_perm + (size_t)b * NN;
    bf16* Ab = A + (size_t)b * NN * NN;
    float* degB = deg + (size_t)b * NN;
    const int tid = threadIdx.x;

    if (as[j0] > as[i0 + 63] + 0.0501f || as[j0 + 63] < as[i0] - 0.0501f) {
        const int r = tid >> 2, c4 = tid & 3;
        float4 z = make_float4(0.f, 0.f, 0.f, 0.f);
        float4* row = (float4*)(Ab + (size_t)(i0 + r) * NN + j0);
        row[c4 * 2] = z;
        row[c4 * 2 + 1] = z;
        if (bi != bj) {
            float4* rowT = (float4*)(Ab + (size_t)(j0 + r) * NN + i0);
            rowT[c4 * 2] = z;
            rowT[c4 * 2 + 1] = z;
        }
        return;
    }

    __shared__ __align__(16) char sbuf[17408];
    float (*sXi)[68] = (float (*)[68])sbuf;
    float (*sXj)[68] = (float (*)[68])(sbuf + 8704);

    const float* Xb = X + (size_t)b * NN * FF;
    const int tx = tid & 15;
    const int ty = tid >> 4;
    const int lane = tid & 31;

    float acc[4][4];
#pragma unroll
    for (int r = 0; r < 4; ++r)
#pragma unroll
        for (int c = 0; c < 4; ++c) acc[r][c] = 0.f;

    const int lk = tid & 31;
    const int lr = tid >> 5;

    int piR[8], pjR[8];
#pragma unroll
    for (int r = 0; r < 8; ++r) {
        piR[r] = permB[i0 + lr + r * 8];
        pjR[r] = permB[j0 + lr + r * 8];
    }

    for (int k0 = 0; k0 < FF; k0 += 32) {
#pragma unroll
        for (int r = 0; r < 8; ++r) {
            const int row = lr + r * 8;
            const int k = k0 + lk;
            float vi = 0.f, vj = 0.f;
            if (k < FF) {
                vi = Xb[(size_t)piR[r] * FF + k];
                vj = Xb[(size_t)pjR[r] * FF + k];
            }
            sXi[lk][row] = vi;
            sXj[lk][row] = vj;
        }
        __syncthreads();
#pragma unroll
        for (int kk = 0; kk < 32; ++kk) {
            const float4 av = *(const float4*)&sXi[kk][ty * 4];
            const float4 bv = *(const float4*)&sXj[kk][tx * 4];
            const float a_[4] = {av.x, av.y, av.z, av.w};
            const float b_[4] = {bv.x, bv.y, bv.z, bv.w};
#pragma unroll
            for (int r = 0; r < 4; ++r)
#pragma unroll
                for (int c = 0; c < 4; ++c)
                    acc[r][c] += fabsf(a_[r] - b_[c]);
        }
        __syncthreads();
    }

    float ai[4], aj[4];
#pragma unroll
    for (int r = 0; r < 4; ++r) ai[r] = as[i0 + ty * 4 + r];
#pragma unroll
    for (int c = 0; c < 4; ++c) aj[c] = as[j0 + tx * 4 + c];

    unsigned short bits[4][4];
    int cnt[4] = {0, 0, 0, 0};
#pragma unroll
    for (int r = 0; r < 4; ++r) {
        const int i = i0 + ty * 4 + r;
#pragma unroll
        for (int c = 0; c < 4; ++c) {
            const int j = j0 + tx * 4 + c;
            const bool keep = (acc[r][c] <= 180.0f && fabsf(ai[r] - aj[c]) <= 0.05f);
            bits[r][c] = keep ? 0x3F80 : 0;
            cnt[r] += keep ? 1 : 0;
            *(unsigned short*)&Ab[(size_t)i * NN + j] = bits[r][c];
        }
    }

#pragma unroll
    for (int r = 0; r < 4; ++r) {
#pragma unroll
        for (int o = 8; o; o >>= 1)
            cnt[r] += __shfl_down_sync(0xffffffffu, cnt[r], o, 16);
    }
    if ((lane & 15) == 0) {
#pragma unroll
        for (int r = 0; r < 4; ++r)
            atomicAdd(&degB[i0 + ty * 4 + r], (float)cnt[r]);
    }

    if (bi != bj) {
        unsigned short (*sT)[66] = (unsigned short (*)[66])sbuf;
        __syncthreads();
#pragma unroll
        for (int r = 0; r < 4; ++r)
#pragma unroll
            for (int c = 0; c < 4; ++c)
                sT[tx * 4 + c][ty * 4 + r] = bits[r][c];
        __syncthreads();
        const int jr = tid >> 2;
        const int cs = (tid & 3) * 16;
        bf16* dst = Ab + (size_t)(j0 + jr) * NN + i0 + cs;
        int csum = 0;
#pragma unroll
        for (int q = 0; q < 8; ++q) {
            const unsigned short e0 = sT[jr][cs + 2 * q];
            const unsigned short e1 = sT[jr][cs + 2 * q + 1];
            csum += (e0 ? 1 : 0) + (e1 ? 1 : 0);
            uint32_t v = (uint32_t)e0 | ((uint32_t)e1 << 16);
            *(uint32_t*)(dst + 2 * q) = v;
        }
        csum += __shfl_down_sync(0xffffffffu, csum, 2, 4);
        csum += __shfl_down_sync(0xffffffffu, csum, 1, 4);
        if ((tid & 3) == 0) atomicAdd(&degB[j0 + jr], (float)csum);
    }
}

// ---------------------------------------------------------------------------
// Row-based split fp32 -> (hi, lo) bf16, zero-padded; optional perm gather.
// ---------------------------------------------------------------------------
__global__ __launch_bounds__(256) void split_kernel(
    const float* __restrict__ src, bf16* __restrict__ dh, bf16* __restrict__ dl,
    int R, int C, int Cp, long sStride, long dStride,
    const int* __restrict__ perm)
{
    const int r = blockIdx.x;
    const int b = blockIdx.y;
    const long dbase = (long)b * dStride + (long)r * Cp;

    if (r >= R) {
        const bf16 z = __float2bfloat16(0.f);
        for (int c = threadIdx.x; c < Cp; c += 256) {
            dh[dbase + c] = z;
            dl[dbase + c] = z;
        }
        return;
    }
    const int sr = perm ? perm[(long)b * NN + r] : r;
    const float* srow = src + (long)b * sStride + (long)sr * C;
    for (int c = threadIdx.x; c < Cp; c += 256) {
        const float v = (c < C) ? srow[c] : 0.f;
        const bf16 hi = __float2bfloat16(v);
        dh[dbase + c] = hi;
        dl[dbase + c] = __float2bfloat16(v - __bfloat162float(hi));
    }
}

__global__ void biaspad_kernel(const float* __restrict__ b1, const float* __restrict__ b2)
{
    int t = blockIdx.x * 256 + threadIdx.x;
    if (t < FHPN) g_b1p[t] = (t < FH) ? b1[t] : 0.f;
    if (t < FFP)  g_b2p[t] = (t < FF) ? b2[t] : 0.f;
}

// ---------------------------------------------------------------------------
// Tensor-core GEMM: block 128x128, 8 warps (warp tile 64x32), 256 threads.
// DYNAMIC smem: 6-stage ring (16KB/stage = 96KB), prefetch distance 5
// (wait_group 4) -> 5 loads in flight per CTA for DRAM-latency hiding.
// SUPER-GROUPS {A1, B1, A2=A1+a2off?, B2=B1+b2off?}: up to 48 MMAs/step.
// C = op( (1/deg) ⊙ Σ + bias ); band-K prune via atts.
// ---------------------------------------------------------------------------
struct GP {
    const bf16* A[2];
    const bf16* B1[2];
    long a2off[2];          // 0 = no A2 for this group
    long b2off;             // 0 = no B2 (global)
    long sA[2], sB[2];
    int  ngrp, steps;
    int  ldA, ldB;
    float* Cf; bf16* Ch; bf16* Cl;
    long sC; int ldC;
    const float* bias;
    const float* deg;
    const int* outPerm;
    const float* atts;
    int relu, Nlim, splitOut;
};

__device__ __forceinline__ void cp16(uint32_t dst, const void* src) {
    asm volatile("cp.async.cg.shared.global [%0], [%1], 16;\n" :: "r"(dst), "l"(src));
}
__device__ __forceinline__ void ldsm4(uint32_t* r, uint32_t addr) {
    asm volatile("ldmatrix.sync.aligned.m8n8.x4.shared.b16 {%0,%1,%2,%3}, [%4];\n"
                 : "=r"(r[0]), "=r"(r[1]), "=r"(r[2]), "=r"(r[3]) : "r"(addr));
}
__device__ __forceinline__ void ldsm4t(uint32_t* r, uint32_t addr) {
    asm volatile("ldmatrix.sync.aligned.m8n8.x4.trans.shared.b16 {%0,%1,%2,%3}, [%4];\n"
                 : "=r"(r[0]), "=r"(r[1]), "=r"(r[2]), "=r"(r[3]) : "r"(addr));
}
__device__ __forceinline__ void mma16816(float* d, const uint32_t* a, uint32_t b0, uint32_t b1) {
    asm volatile(
        "mma.sync.aligned.m16n8k16.row.col.f32.bf16.bf16.f32 "
        "{%0,%1,%2,%3}, {%4,%5,%6,%7}, {%8,%9}, {%0,%1,%2,%3};\n"
        : "+f"(d[0]), "+f"(d[1]), "+f"(d[2]), "+f"(d[3])
        : "r"(a[0]), "r"(a[1]), "r"(a[2]), "r"(a[3]), "r"(b0), "r"(b1));
}

#define STGB 16384           // stage: A1 4KB + B1 4KB + B2 4KB + A2 4KB
#define NSTG 6
#define SMEM_DYN (NSTG * STGB)   // 96KB -> 2 CTAs/SM = 192KB of 227KB

__global__ __launch_bounds__(256, 2) void mma_gemm(GP p)
{
    extern __shared__ __align__(128) char smem[];
    const uint32_t sbase = (uint32_t)__cvta_generic_to_shared(smem);

    const int tid  = threadIdx.x;
    const int lane = tid & 31;
    const int warp = tid >> 5;
    const int b  = blockIdx.z;
    const int m0 = blockIdx.y * 128;
    const int n0 = blockIdx.x * 128;
    const int wm = (warp & 1) * 64;
    const int wn = (warp >> 1) * 32;

    // band-K restriction for adjacency GEMMs
    int sStart = 0, sEnd = p.steps;
    if (p.atts) {
        const float* as = p.atts + (long)b * NN;
        const float lo = as[m0] - 0.0501f;
        const float hi = as[m0 + 127] + 0.0501f;
        int l = 0, r = NN;
        while (l < r) { int mid = (l + r) >> 1; if (as[mid] < lo) l = mid + 1; else r = mid; }
        const int kLo = l;
        l = 0; r = NN;
        while (l < r) { int mid = (l + r) >> 1; if (as[mid] <= hi) l = mid + 1; else r = mid; }
        const int kHi = l;
        sStart = kLo >> 4;
        sEnd   = (kHi + 15) >> 4;
    }
    const int segSteps = sEnd - sStart;
    const int total = p.ngrp * segSteps;
    const bool hasB2 = (p.b2off != 0);

    float acc[4][4][4];
#pragma unroll
    for (int i = 0; i < 4; ++i)
#pragma unroll
        for (int j = 0; j < 4; ++j)
#pragma unroll
            for (int k = 0; k < 4; ++k) acc[i][j][k] = 0.f;

    // producer mapping
    const int ar = tid >> 1, ac = tid & 1;     // A: 128 rows x 2 chunks
    const int bk = tid >> 4, bc = tid & 15;    // B: 16 rows x 16 chunks
    const uint32_t aDst = (uint32_t)((ar * 2 + (ac ^ ((ar >> 2) & 1))) * 16);
    const uint32_t bDst = (uint32_t)((bk * 16 + (bc ^ (bk & 7))) * 16);

    uint32_t aLd[4], bLd[2];
#pragma unroll
    for (int f = 0; f < 4; ++f) {
        const int r = wm + f * 16 + (lane & 15);
        const int c = (lane >> 4) & 1;
        aLd[f] = (uint32_t)((r * 2 + (c ^ ((r >> 2) & 1))) * 16);
    }
#pragma unroll
    for (int g = 0; g < 2; ++g) {
        const int kk = lane & 15;
        const int cn = (wn >> 3) + g * 2 + ((lane >> 4) & 1);
        bLd[g] = (uint32_t)((kk * 16 + (cn ^ (kk & 7))) * 16);
    }

    const long aOff = (long)(m0 + ar) * p.ldA + ac * 8;
    const long bOff = (long)bk * p.ldB + n0 + bc * 8;
    const bf16* Ag  = p.A[0]  + (long)b * p.sA[0] + aOff;
    const bf16* B1g = p.B1[0] + (long)b * p.sB[0] + bOff;
    long a2o = p.a2off[0];
    int pGrp = 0, pKs = 0;

    auto issue = [&](int stage) {
        const uint32_t base = sbase + (uint32_t)stage * STGB;
        const long ks = (long)(sStart + pKs);
        const bf16* as_ = Ag + ks * 16;
        const bf16* bs_ = B1g + ks * 16 * p.ldB;
        cp16(base + aDst, as_);
        cp16(base + 4096 + bDst, bs_);
        if (hasB2) cp16(base + 8192 + bDst, bs_ + p.b2off);
        if (a2o)   cp16(base + 12288 + aDst, as_ + a2o);
        if (++pKs == segSteps) {
            pKs = 0;
            if (++pGrp < p.ngrp) {
                Ag  = p.A[pGrp]  + (long)b * p.sA[pGrp] + aOff;
                B1g = p.B1[pGrp] + (long)b * p.sB[pGrp] + bOff;
                a2o = p.a2off[pGrp];
            }
        }
    };

    // prologue: 5 stages in flight (prefetch distance 5; total >= 13 always)
#pragma unroll
    for (int i = 0; i < 5; ++i) {
        if (i < total) issue(i);
        asm volatile("cp.async.commit_group;\n");
    }

    int cStage = 0, iStage = 5;
    int cGrp = 0, cKs = 0;
    for (int s = 0; s < total; ++s) {
        asm volatile("cp.async.wait_group 4;\n");
        __syncthreads();

        const uint32_t so = sbase + (uint32_t)cStage * STGB;
        uint32_t afr[4][4], bfr[2][4], b2fr[2][4];
#pragma unroll
        for (int f = 0; f < 4; ++f) ldsm4(afr[f], so + aLd[f]);
#pragma unroll
        for (int g = 0; g < 2; ++g) ldsm4t(bfr[g], so + 4096 + bLd[g]);
        if (hasB2) {
#pragma unroll
            for (int g = 0; g < 2; ++g) ldsm4t(b2fr[g], so + 8192 + bLd[g]);
        }
        const bool hasA2 = (p.a2off[cGrp] != 0);

        if (s + 5 < total) issue(iStage);      // stage != cStage — no collision
        asm volatile("cp.async.commit_group;\n");
        cStage = (cStage + 1 == NSTG) ? 0 : cStage + 1;
        iStage = (iStage + 1 == NSTG) ? 0 : iStage + 1;

#pragma unroll
        for (int mf = 0; mf < 4; ++mf)
#pragma unroll
            for (int nf = 0; nf < 4; ++nf) {
                const uint32_t* bb = bfr[nf >> 1];
                const int sub = (nf & 1) * 2;
                mma16816(acc[mf][nf], afr[mf], bb[sub], bb[sub + 1]);
            }
        if (hasB2) {
#pragma unroll
            for (int mf = 0; mf < 4; ++mf)
#pragma unroll
                for (int nf = 0; nf < 4; ++nf) {
                    const uint32_t* bb = b2fr[nf >> 1];
                    const int sub = (nf & 1) * 2;
                    mma16816(acc[mf][nf], afr[mf], bb[sub], bb[sub + 1]);
                }
        }
        if (hasA2) {
#pragma unroll
            for (int f = 0; f < 4; ++f) ldsm4(afr[f], so + 12288 + aLd[f]);
#pragma unroll
            for (int mf = 0; mf < 4; ++mf)
#pragma unroll
                for (int nf = 0; nf < 4; ++nf) {
                    const uint32_t* bb = bfr[nf >> 1];
                    const int sub = (nf & 1) * 2;
                    mma16816(acc[mf][nf], afr[mf], bb[sub], bb[sub + 1]);
                }
        }

        if (++cKs == segSteps) { cKs = 0; ++cGrp; }
    }

    asm volatile("cp.async.wait_group 0;\n");
    __syncthreads();

    // ---------------- epilogue (single pass per 64-row half) ----------------
    const float* dgB = p.deg ? (p.deg + (long)b * NN) : nullptr;
    const int* opB = p.outPerm ? (p.outPerm + (long)b * NN) : nullptr;

    if (p.splitOut) {
        uint32_t* sH = (uint32_t*)smem;
        uint32_t* sL = sH + 64 * 68;
        for (int h = 0; h < 2; ++h) {
            if (wm == h * 64) {
#pragma unroll
                for (int mf = 0; mf < 4; ++mf) {
                    const int rA = mf * 16 + (lane >> 2);
                    const int gRow = m0 + h * 64 + rA;
                    const float rs0 = dgB ? (1.0f / dgB[gRow]) : 1.f;
                    const float rs1 = dgB ? (1.0f / dgB[gRow + 8]) : 1.f;
#pragma unroll
                    for (int nf = 0; nf < 4; ++nf) {
                        const int nL = wn + nf * 8 + (lane & 3) * 2;
                        float v[4] = {acc[mf][nf][0] * rs0, acc[mf][nf][1] * rs0,
                                      acc[mf][nf][2] * rs1, acc[mf][nf][3] * rs1};
                        if (p.bias) {
                            const float bz0 = p.bias[n0 + nL], bz1 = p.bias[n0 + nL + 1];
                            v[0] += bz0; v[1] += bz1; v[2] += bz0; v[3] += bz1;
                        }
                        if (p.relu) {
#pragma unroll
                            for (int q = 0; q < 4; ++q) v[q] = fmaxf(v[q], 0.f);
                        }
                        unsigned short oh[4], ol[4];
#pragma unroll
                        for (int q = 0; q < 4; ++q) {
                            const bf16 hi = __float2bfloat16(v[q]);
                            oh[q] = __bfloat16_as_ushort(hi);
                            ol[q] = __bfloat16_as_ushort(
                                __float2bfloat16(v[q] - __bfloat162float(hi)));
                        }
                        const int cu = (nL >> 1);
                        sH[rA * 68 + cu]       = (uint32_t)oh[0] | ((uint32_t)oh[1] << 16);
                        sH[(rA + 8) * 68 + cu] = (uint32_t)oh[2] | ((uint32_t)oh[3] << 16);
                        sL[rA * 68 + cu]       = (uint32_t)ol[0] | ((uint32_t)ol[1] << 16);
                        sL[(rA + 8) * 68 + cu] = (uint32_t)ol[2] | ((uint32_t)ol[3] << 16);
                    }
                }
            }
            __syncthreads();
            {
                const int r = tid >> 2, q = tid & 3;
                const long off = (long)b * p.sC + (long)(m0 + h * 64 + r) * p.ldC + n0;
                uint4* dH = (uint4*)(p.Ch + off);
                uint4* dL = (uint4*)(p.Cl + off);
                const uint4* rH = (const uint4*)(sH + r * 68);
                const uint4* rL = (const uint4*)(sL + r * 68);
#pragma unroll
                for (int i = 0; i < 4; ++i) {
                    dH[q * 4 + i] = rH[q * 4 + i];
                    dL[q * 4 + i] = rL[q * 4 + i];
                }
            }
            __syncthreads();
        }
    } else {
        float* sF = (float*)smem;   // 64 rows x 132 f32
        for (int h = 0; h < 2; ++h) {
            if (wm == h * 64) {
#pragma unroll
                for (int mf = 0; mf < 4; ++mf) {
                    const int rA = mf * 16 + (lane >> 2);
#pragma unroll
                    for (int nf = 0; nf < 4; ++nf) {
                        const int nL = wn + nf * 8 + (lane & 3) * 2;
                        float v[4] = {acc[mf][nf][0], acc[mf][nf][1],
                                      acc[mf][nf][2], acc[mf][nf][3]};
                        if (p.bias) {
                            const float bz0 = p.bias[n0 + nL], bz1 = p.bias[n0 + nL + 1];
                            v[0] += bz0; v[1] += bz1; v[2] += bz0; v[3] += bz1;
                        }
                        if (p.relu) {
#pragma unroll
                            for (int q = 0; q < 4; ++q) v[q] = fmaxf(v[q], 0.f);
                        }
                        sF[rA * 132 + nL]           = v[0];
                        sF[rA * 132 + nL + 1]       = v[1];
                        sF[(rA + 8) * 132 + nL]     = v[2];
                        sF[(rA + 8) * 132 + nL + 1] = v[3];
                    }
                }
            }
            __syncthreads();
            {
                const int colL = tid & 127;
                const int rb = tid >> 7;
                const int n = n0 + colL;
                if (n < p.Nlim) {
#pragma unroll
                    for (int i = 0; i < 32; ++i) {
                        const int rA = rb + 2 * i;
                        const int row = m0 + h * 64 + rA;
                        const int mo = opB ? opB[row] : row;
                        p.Cf[(long)b * p.sC + (long)mo * p.ldC + n] = sF[rA * 132 + colL];
                    }
                }
            }
            __syncthreads();
        }
    }
}

// ---------------------------------------------------------------------------
extern "C" void kernel_launch(void* const* d_in, const int* in_sizes, int n_in,
                              void* d_out, int out_size)
{
    const float* x4  = (const float*)d_in[0];
    const float* att = (const float*)d_in[1];
    const float* W1  = (const float*)d_in[2];
    const float* b1  = (const float*)d_in[3];
    const float* W2  = (const float*)d_in[4];
    const float* b2  = (const float*)d_in[5];
    float* out = (float*)d_out;

    // dynamic-smem opt-in (not a stream op; graph-capture safe; idempotent)
    cudaFuncSetAttribute(mma_gemm, cudaFuncAttributeMaxDynamicSharedMemorySize, SMEM_DYN);

    void *pA, *pDeg, *pPerm, *pAtts, *pXh, *pXl, *pTh, *pTl, *phh, *phl, *pT2h, *pT2l;
    void *pW1h, *pW1l, *pW2h, *pW2l, *pb1p, *pb2p;
    cudaGetSymbolAddress(&pA, g_A);
    cudaGetSymbolAddress(&pDeg, g_deg);
    cudaGetSymbolAddress(&pPerm, g_perm);
    cudaGetSymbolAddress(&pAtts, g_atts);
    cudaGetSymbolAddress(&pXh, g_Xh);  cudaGetSymbolAddress(&pXl, g_Xl);
    cudaGetSymbolAddress(&pTh, g_Th);  cudaGetSymbolAddress(&pTl, g_Tl);
    cudaGetSymbolAddress(&phh, g_hh);  cudaGetSymbolAddress(&phl, g_hl);
    cudaGetSymbolAddress(&pT2h, g_T2h); cudaGetSymbolAddress(&pT2l, g_T2l);
    cudaGetSymbolAddress(&pW1h, g_W1h); cudaGetSymbolAddress(&pW1l, g_W1l);
    cudaGetSymbolAddress(&pW2h, g_W2h); cudaGetSymbolAddress(&pW2l, g_W2l);
    cudaGetSymbolAddress(&pb1p, g_b1p); cudaGetSymbolAddress(&pb2p, g_b2p);

    bf16 *Ab = (bf16*)pA;
    float *deg = (float*)pDeg;
    int *perm = (int*)pPerm;
    float *atts = (float*)pAtts;
    bf16 *Xh = (bf16*)pXh, *Xl = (bf16*)pXl;
    bf16 *Th = (bf16*)pTh, *Tl = (bf16*)pTl;
    bf16 *hh = (bf16*)phh, *hl = (bf16*)phl;
    bf16 *T2h = (bf16*)pT2h, *T2l = (bf16*)pT2l;
    bf16 *W1h = (bf16*)pW1h, *W1l = (bf16*)pW1l;
    bf16 *W2h = (bf16*)pW2h, *W2l = (bf16*)pW2l;
    float *b1p = (float*)pb1p, *b2p = (float*)pb2p;

    // 0: sort (also zeroes deg)
    sort_kernel<<<BB, 512>>>(att);
    // 1: adjacency (band-pruned, symmetric) + degree atomics
    adj_kernel<<<dim3(8, 8, BB), 256>>>(x4, Ab, deg);
    // 2: X split (sorted gather), row-based
    split_kernel<<<dim3(NN, BB), 256>>>(
        x4, Xh, Xl, NN, FF, FFP, (long)NN * FF, (long)NN * FFP, perm);

    // 3: bmm1: T = (1/deg) ⊙ A@(Xh,Xl)  [band-K; B2 = Xl via offset]
    {
        GP p = {};
        p.A[0] = Ab; p.B1[0] = Xh;
        p.b2off = Xl - Xh;
        p.sA[0] = (long)NN * NN; p.sB[0] = (long)NN * FFP;
        p.ngrp = 1; p.steps = NN / 16; p.ldA = NN; p.ldB = FFP;
        p.Ch = Th; p.Cl = Tl; p.sC = (long)NN * FFP; p.ldC = FFP;
        p.deg = deg; p.atts = atts;
        p.bias = nullptr; p.relu = 0; p.Nlim = FFP; p.splitOut = 1;
        mma_gemm<<<dim3(FFP / 128, NN / 128, BB), 256, SMEM_DYN>>>(p);
    }

    // 4: W1 split, row-based
    split_kernel<<<dim3(FFP, 2), 256>>>(
        W1, W1h, W1l, FF, FH, FHPN, (long)FF * FH, (long)FFP * FHPN, nullptr);
    // 5: bias pad
    biaspad_kernel<<<dim3((FHPN + 255) / 256), 256>>>(b1, b2);

    // 6: layer1: super-groups {Xh, W10h, A2=Xl, B2=W10l}, {Th, W11h, A2=Tl, B2=W11l}
    {
        GP p = {};
        const bf16* W10h = W1h;
        const bf16* W11h = W1h + (size_t)FFP * FHPN;
        p.A[0] = Xh; p.B1[0] = W10h; p.a2off[0] = Xl - Xh;
        p.A[1] = Th; p.B1[1] = W11h; p.a2off[1] = Tl - Th;
        p.b2off = W1l - W1h;
        for (int i = 0; i < 2; ++i) { p.sA[i] = (long)NN * FFP; p.sB[i] = 0; }
        p.ngrp = 2; p.steps = FFP / 16; p.ldA = FFP; p.ldB = FHPN;
        p.Ch = hh; p.Cl = hl; p.sC = (long)NN * FHPN; p.ldC = FHPN;
        p.bias = b1p; p.relu = 1; p.Nlim = FHPN; p.splitOut = 1;
        mma_gemm<<<dim3(FHPN / 128, NN / 128, BB), 256, SMEM_DYN>>>(p);
    }

    // 7: bmm2: T2 = (1/deg) ⊙ A@(hh,hl)  [band-K; B2 = hl via offset]
    {
        GP p = {};
        p.A[0] = Ab; p.B1[0] = hh;
        p.b2off = hl - hh;
        p.sA[0] = (long)NN * NN; p.sB[0] = (long)NN * FHPN;
        p.ngrp = 1; p.steps = NN / 16; p.ldA = NN; p.ldB = FHPN;
        p.Ch = T2h; p.Cl = T2l; p.sC = (long)NN * FHPN; p.ldC = FHPN;
        p.deg = deg; p.atts = atts;
        p.bias = nullptr; p.relu = 0; p.Nlim = FHPN; p.splitOut = 1;
        mma_gemm<<<dim3(FHPN / 128, NN / 128, BB), 256, SMEM_DYN>>>(p);
    }

    // 8: W2 split, row-based
    split_kernel<<<dim3(FHPK, 2), 256>>>(
        W2, W2h, W2l, FH, FF, FFP, (long)FH * FF, (long)FHPK * FFP, nullptr);

    // 9: layer2: super-groups {hh, W20h, A2=hl, B2=W20l}, {T2h, W21h, A2=T2l, B2=W21l}
    {
        GP p = {};
        const bf16* W20h = W2h;
        const bf16* W21h = W2h + (size_t)FHPK * FFP;
        p.A[0] = hh;  p.B1[0] = W20h; p.a2off[0] = hl - hh;
        p.A[1] = T2h; p.B1[1] = W21h; p.a2off[1] = T2l - T2h;
        p.b2off = W2l - W2h;
        for (int i = 0; i < 2; ++i) { p.sA[i] = (long)NN * FHPN; p.sB[i] = 0; }
        p.ngrp = 2; p.steps = FHPK / 16; p.ldA = FHPN; p.ldB = FFP;
        p.Cf = out; p.sC = (long)NN * FF; p.ldC = FF;
        p.outPerm = perm;
        p.bias = b2p; p.relu = 1; p.Nlim = FF; p.splitOut = 0;
        mma_gemm<<<dim3(FFP / 128, NN / 128, BB), 256, SMEM_DYN>>>(p);
    }
}

// round 16
// speedup vs baseline: 1.1092x; 1.1092x over previous
#include <cuda_runtime.h>
#include <cuda_bf16.h>
#include <cstdint>

#define BB 16
#define NN 512
#define FF 625
#define FH 937
#define FFP 640      // F padded (mult of 128)
#define FHPN 1024    // Fh padded for N-dim (mult of 128)
#define FHPK 944     // Fh padded for K-dim (mult of 16)

typedef __nv_bfloat16 bf16;

// ---------------- scratch (no allocs allowed -> device globals) -------------
__device__ bf16  g_A[(size_t)BB * NN * NN];   // adjacency 0/1 in SORTED space
__device__ float g_deg[(size_t)BB * NN];      // row degree (exact integer in fp32)
__device__ float g_atts[(size_t)BB * NN];     // sorted att values
__device__ int   g_perm[(size_t)BB * NN];     // perm[i] = original index of i-th smallest

__device__ bf16 g_Xh[(size_t)BB * NN * FFP],  g_Xl[(size_t)BB * NN * FFP];
__device__ bf16 g_Th[(size_t)BB * NN * FFP],  g_Tl[(size_t)BB * NN * FFP];
__device__ bf16 g_hh[(size_t)BB * NN * FHPN], g_hl[(size_t)BB * NN * FHPN];
__device__ bf16 g_T2h[(size_t)BB * NN * FHPN], g_T2l[(size_t)BB * NN * FHPN];
__device__ bf16 g_W1h[2ul * FFP * FHPN],  g_W1l[2ul * FFP * FHPN];
__device__ bf16 g_W2h[2ul * FHPK * FFP],  g_W2l[2ul * FHPK * FFP];
__device__ float g_b1p[FHPN], g_b2p[FFP];

// ---------------------------------------------------------------------------
// Kernel 0: bitonic sort of att per batch; also zeroes deg.
// ---------------------------------------------------------------------------
__global__ __launch_bounds__(512) void sort_kernel(const float* __restrict__ att)
{
    __shared__ float key[NN];
    __shared__ int   idx[NN];
    const int b = blockIdx.x;
    const int t = threadIdx.x;

    g_deg[(size_t)b * NN + t] = 0.f;

    key[t] = att[(size_t)b * NN + t];
    idx[t] = t;
    __syncthreads();

    for (int sz = 2; sz <= NN; sz <<= 1) {
        for (int st = sz >> 1; st > 0; st >>= 1) {
            const int p = t ^ st;
            if (p > t) {
                const bool up = ((t & sz) == 0);
                const float a = key[t], c = key[p];
                if (up ? (a > c) : (a < c)) {
                    key[t] = c; key[p] = a;
                    const int ia = idx[t]; idx[t] = idx[p]; idx[p] = ia;
                }
            }
            __syncthreads();
        }
    }
    g_atts[(size_t)b * NN + t] = key[t];
    g_perm[(size_t)b * NN + t] = idx[t];
}

// ---------------------------------------------------------------------------
// Kernel 1: thresholded adjacency in sorted space (band prune + symmetry),
// with exact row-degree accumulation via float atomicAdd.
// ---------------------------------------------------------------------------
__global__ __launch_bounds__(256) void adj_kernel(
    const float* __restrict__ X, bf16* __restrict__ A, float* __restrict__ deg)
{
    const int b  = blockIdx.z;
    const int bi = blockIdx.y;
    const int bj = blockIdx.x;
    if (bj < bi) return;
    const int i0 = bi * 64;
    const int j0 = bj * 64;
    const float* as = g_atts + (size_t)b * NN;
    const int* permB = g_perm + (size_t)b * NN;
    bf16* Ab = A + (size_t)b * NN * NN;
    float* degB = deg + (size_t)b * NN;
    const int tid = threadIdx.x;

    if (as[j0] > as[i0 + 63] + 0.0501f || as[j0 + 63] < as[i0] - 0.0501f) {
        const int r = tid >> 2, c4 = tid & 3;
        float4 z = make_float4(0.f, 0.f, 0.f, 0.f);
        float4* row = (float4*)(Ab + (size_t)(i0 + r) * NN + j0);
        row[c4 * 2] = z;
        row[c4 * 2 + 1] = z;
        if (bi != bj) {
            float4* rowT = (float4*)(Ab + (size_t)(j0 + r) * NN + i0);
            rowT[c4 * 2] = z;
            rowT[c4 * 2 + 1] = z;
        }
        return;
    }

    __shared__ __align__(16) char sbuf[17408];
    float (*sXi)[68] = (float (*)[68])sbuf;
    float (*sXj)[68] = (float (*)[68])(sbuf + 8704);

    const float* Xb = X + (size_t)b * NN * FF;
    const int tx = tid & 15;
    const int ty = tid >> 4;
    const int lane = tid & 31;

    float acc[4][4];
#pragma unroll
    for (int r = 0; r < 4; ++r)
#pragma unroll
        for (int c = 0; c < 4; ++c) acc[r][c] = 0.f;

    const int lk = tid & 31;
    const int lr = tid >> 5;

    int piR[8], pjR[8];
#pragma unroll
    for (int r = 0; r < 8; ++r) {
        piR[r] = permB[i0 + lr + r * 8];
        pjR[r] = permB[j0 + lr + r * 8];
    }

    for (int k0 = 0; k0 < FF; k0 += 32) {
#pragma unroll
        for (int r = 0; r < 8; ++r) {
            const int row = lr + r * 8;
            const int k = k0 + lk;
            float vi = 0.f, vj = 0.f;
            if (k < FF) {
                vi = Xb[(size_t)piR[r] * FF + k];
                vj = Xb[(size_t)pjR[r] * FF + k];
            }
            sXi[lk][row] = vi;
            sXj[lk][row] = vj;
        }
        __syncthreads();
#pragma unroll
        for (int kk = 0; kk < 32; ++kk) {
            const float4 av = *(const float4*)&sXi[kk][ty * 4];
            const float4 bv = *(const float4*)&sXj[kk][tx * 4];
            const float a_[4] = {av.x, av.y, av.z, av.w};
            const float b_[4] = {bv.x, bv.y, bv.z, bv.w};
#pragma unroll
            for (int r = 0; r < 4; ++r)
#pragma unroll
                for (int c = 0; c < 4; ++c)
                    acc[r][c] += fabsf(a_[r] - b_[c]);
        }
        __syncthreads();
    }

    float ai[4], aj[4];
#pragma unroll
    for (int r = 0; r < 4; ++r) ai[r] = as[i0 + ty * 4 + r];
#pragma unroll
    for (int c = 0; c < 4; ++c) aj[c] = as[j0 + tx * 4 + c];

    unsigned short bits[4][4];
    int cnt[4] = {0, 0, 0, 0};
#pragma unroll
    for (int r = 0; r < 4; ++r) {
        const int i = i0 + ty * 4 + r;
#pragma unroll
        for (int c = 0; c < 4; ++c) {
            const int j = j0 + tx * 4 + c;
            const bool keep = (acc[r][c] <= 180.0f && fabsf(ai[r] - aj[c]) <= 0.05f);
            bits[r][c] = keep ? 0x3F80 : 0;
            cnt[r] += keep ? 1 : 0;
            *(unsigned short*)&Ab[(size_t)i * NN + j] = bits[r][c];
        }
    }

#pragma unroll
    for (int r = 0; r < 4; ++r) {
#pragma unroll
        for (int o = 8; o; o >>= 1)
            cnt[r] += __shfl_down_sync(0xffffffffu, cnt[r], o, 16);
    }
    if ((lane & 15) == 0) {
#pragma unroll
        for (int r = 0; r < 4; ++r)
            atomicAdd(&degB[i0 + ty * 4 + r], (float)cnt[r]);
    }

    if (bi != bj) {
        unsigned short (*sT)[66] = (unsigned short (*)[66])sbuf;
        __syncthreads();
#pragma unroll
        for (int r = 0; r < 4; ++r)
#pragma unroll
            for (int c = 0; c < 4; ++c)
                sT[tx * 4 + c][ty * 4 + r] = bits[r][c];
        __syncthreads();
        const int jr = tid >> 2;
        const int cs = (tid & 3) * 16;
        bf16* dst = Ab + (size_t)(j0 + jr) * NN + i0 + cs;
        int csum = 0;
#pragma unroll
        for (int q = 0; q < 8; ++q) {
            const unsigned short e0 = sT[jr][cs + 2 * q];
            const unsigned short e1 = sT[jr][cs + 2 * q + 1];
            csum += (e0 ? 1 : 0) + (e1 ? 1 : 0);
            uint32_t v = (uint32_t)e0 | ((uint32_t)e1 << 16);
            *(uint32_t*)(dst + 2 * q) = v;
        }
        csum += __shfl_down_sync(0xffffffffu, csum, 2, 4);
        csum += __shfl_down_sync(0xffffffffu, csum, 1, 4);
        if ((tid & 3) == 0) atomicAdd(&degB[j0 + jr], (float)csum);
    }
}

// ---------------------------------------------------------------------------
// Row-based split fp32 -> (hi, lo) bf16, zero-padded; optional perm gather.
// ---------------------------------------------------------------------------
__global__ __launch_bounds__(256) void split_kernel(
    const float* __restrict__ src, bf16* __restrict__ dh, bf16* __restrict__ dl,
    int R, int C, int Cp, long sStride, long dStride,
    const int* __restrict__ perm)
{
    const int r = blockIdx.x;
    const int b = blockIdx.y;
    const long dbase = (long)b * dStride + (long)r * Cp;

    if (r >= R) {
        const bf16 z = __float2bfloat16(0.f);
        for (int c = threadIdx.x; c < Cp; c += 256) {
            dh[dbase + c] = z;
            dl[dbase + c] = z;
        }
        return;
    }
    const int sr = perm ? perm[(long)b * NN + r] : r;
    const float* srow = src + (long)b * sStride + (long)sr * C;
    for (int c = threadIdx.x; c < Cp; c += 256) {
        const float v = (c < C) ? srow[c] : 0.f;
        const bf16 hi = __float2bfloat16(v);
        dh[dbase + c] = hi;
        dl[dbase + c] = __float2bfloat16(v - __bfloat162float(hi));
    }
}

__global__ void biaspad_kernel(const float* __restrict__ b1, const float* __restrict__ b2)
{
    int t = blockIdx.x * 256 + threadIdx.x;
    if (t < FHPN) g_b1p[t] = (t < FH) ? b1[t] : 0.f;
    if (t < FFP)  g_b2p[t] = (t < FF) ? b2[t] : 0.f;
}

// ---------------------------------------------------------------------------
// Tensor-core GEMM v4: block tile 128x64, 8 warps (warp tile 32x32, 4m x 2n),
// 256 threads, 3 CTAs/SM (24 warps/SM). 4-stage ring (12KB/stage, dynamic),
// prefetch distance 3 (wait_group 2).
// SUPER-GROUPS {A1, B1(+B2 always), A2=A1+a2off?}: A1·B1 + A1·B2 [+ A2·B1].
// C = op( (1/deg) ⊙ Σ + bias ); band-K prune via atts.
// ---------------------------------------------------------------------------
struct GP {
    const bf16* A[2];
    const bf16* B1[2];
    long a2off[2];          // 0 = no A2 for this group
    long b2off;             // always nonzero in our launches
    long sA[2], sB[2];
    int  ngrp, steps;
    int  ldA, ldB;
    float* Cf; bf16* Ch; bf16* Cl;
    long sC; int ldC;
    const float* bias;
    const float* deg;
    const int* outPerm;
    const float* atts;
    int relu, Nlim, splitOut;
};

__device__ __forceinline__ void cp16(uint32_t dst, const void* src) {
    asm volatile("cp.async.cg.shared.global [%0], [%1], 16;\n" :: "r"(dst), "l"(src));
}
__device__ __forceinline__ void ldsm4(uint32_t* r, uint32_t addr) {
    asm volatile("ldmatrix.sync.aligned.m8n8.x4.shared.b16 {%0,%1,%2,%3}, [%4];\n"
                 : "=r"(r[0]), "=r"(r[1]), "=r"(r[2]), "=r"(r[3]) : "r"(addr));
}
__device__ __forceinline__ void ldsm4t(uint32_t* r, uint32_t addr) {
    asm volatile("ldmatrix.sync.aligned.m8n8.x4.trans.shared.b16 {%0,%1,%2,%3}, [%4];\n"
                 : "=r"(r[0]), "=r"(r[1]), "=r"(r[2]), "=r"(r[3]) : "r"(addr));
}
__device__ __forceinline__ void mma16816(float* d, const uint32_t* a, uint32_t b0, uint32_t b1) {
    asm volatile(
        "mma.sync.aligned.m16n8k16.row.col.f32.bf16.bf16.f32 "
        "{%0,%1,%2,%3}, {%4,%5,%6,%7}, {%8,%9}, {%0,%1,%2,%3};\n"
        : "+f"(d[0]), "+f"(d[1]), "+f"(d[2]), "+f"(d[3])
        : "r"(a[0]), "r"(a[1]), "r"(a[2]), "r"(a[3]), "r"(b0), "r"(b1));
}

#define STGB 12288           // stage: A1 4KB @0 + B1 2KB @4096 + B2 2KB @6144 + A2 4KB @8192
#define NSTG 4
#define SMEM_DYN (NSTG * STGB)   // 48KB -> 3 CTAs/SM = 144KB of 227KB

__global__ __launch_bounds__(256, 3) void mma_gemm(GP p)
{
    extern __shared__ __align__(128) char smem[];
    const uint32_t sbase = (uint32_t)__cvta_generic_to_shared(smem);

    const int tid  = threadIdx.x;
    const int lane = tid & 31;
    const int warp = tid >> 5;
    const int b  = blockIdx.z;
    const int m0 = blockIdx.y * 128;
    const int n0 = blockIdx.x * 64;
    const int wm = (warp & 3) * 32;        // 4 m-warps
    const int wn = (warp >> 2) * 32;       // 2 n-warps

    // band-K restriction for adjacency GEMMs
    int sStart = 0, sEnd = p.steps;
    if (p.atts) {
        const float* as = p.atts + (long)b * NN;
        const float lo = as[m0] - 0.0501f;
        const float hi = as[m0 + 127] + 0.0501f;
        int l = 0, r = NN;
        while (l < r) { int mid = (l + r) >> 1; if (as[mid] < lo) l = mid + 1; else r = mid; }
        const int kLo = l;
        l = 0; r = NN;
        while (l < r) { int mid = (l + r) >> 1; if (as[mid] <= hi) l = mid + 1; else r = mid; }
        const int kHi = l;
        sStart = kLo >> 4;
        sEnd   = (kHi + 15) >> 4;
    }
    const int segSteps = sEnd - sStart;
    const int total = p.ngrp * segSteps;

    float acc[2][4][4];
#pragma unroll
    for (int i = 0; i < 2; ++i)
#pragma unroll
        for (int j = 0; j < 4; ++j)
#pragma unroll
            for (int k = 0; k < 4; ++k) acc[i][j][k] = 0.f;

    // producers: A 128x16 by all 256 threads; B1 by tids 0-127, B2 by 128-255
    const int ar = tid >> 1, ac = tid & 1;
    const uint32_t aDst = (uint32_t)((ar * 2 + (ac ^ ((ar >> 2) & 1))) * 16);
    const int bt = tid & 127;
    const int bk = bt >> 3, bc = bt & 7;   // 16 rows x 8 chunks (64 cols)
    const uint32_t bDst = (uint32_t)(((tid < 128 ? 4096 : 6144)) +
                                     (bk * 8 + (bc ^ (bk & 7))) * 16);

    uint32_t aLd[2], bLd[2];
#pragma unroll
    for (int f = 0; f < 2; ++f) {
        const int r = wm + f * 16 + (lane & 15);
        const int c = (lane >> 4) & 1;
        aLd[f] = (uint32_t)((r * 2 + (c ^ ((r >> 2) & 1))) * 16);
    }
#pragma unroll
    for (int g = 0; g < 2; ++g) {
        const int kk = lane & 15;
        const int cn = (wn >> 3) + g * 2 + ((lane >> 4) & 1);
        bLd[g] = (uint32_t)((kk * 8 + (cn ^ (kk & 7))) * 16);
    }

    const long aOff = (long)(m0 + ar) * p.ldA + ac * 8;
    const long bOff = (long)bk * p.ldB + n0 + bc * 8 + (tid < 128 ? 0 : p.b2off);
    const bf16* Ag  = p.A[0]  + (long)b * p.sA[0] + aOff;
    const bf16* Bg  = p.B1[0] + (long)b * p.sB[0] + bOff;
    long a2o = p.a2off[0];
    int pGrp = 0, pKs = 0;

    auto issue = [&](int stage) {
        const uint32_t base = sbase + (uint32_t)stage * STGB;
        const long ks = (long)(sStart + pKs);
        const bf16* as_ = Ag + ks * 16;
        cp16(base + aDst, as_);
        cp16(base + bDst, Bg + ks * 16 * p.ldB);
        if (a2o) cp16(base + 8192 + aDst, as_ + a2o);
        if (++pKs == segSteps) {
            pKs = 0;
            if (++pGrp < p.ngrp) {
                Ag = p.A[pGrp]  + (long)b * p.sA[pGrp] + aOff;
                Bg = p.B1[pGrp] + (long)b * p.sB[pGrp] + bOff;
                a2o = p.a2off[pGrp];
            }
        }
    };

    // prologue: 3 stages in flight (prefetch distance 3)
#pragma unroll
    for (int i = 0; i < 3; ++i) {
        if (i < total) issue(i);
        asm volatile("cp.async.commit_group;\n");
    }

    int cGrp = 0, cKs = 0;
    for (int s = 0; s < total; ++s) {
        asm volatile("cp.async.wait_group 2;\n");
        __syncthreads();

        const uint32_t so = sbase + (uint32_t)(s & 3) * STGB;
        uint32_t afr[2][4], bfr[2][4], b2fr[2][4];
#pragma unroll
        for (int f = 0; f < 2; ++f) ldsm4(afr[f], so + aLd[f]);
#pragma unroll
        for (int g = 0; g < 2; ++g) ldsm4t(bfr[g], so + 4096 + bLd[g]);
#pragma unroll
        for (int g = 0; g < 2; ++g) ldsm4t(b2fr[g], so + 6144 + bLd[g]);
        const bool hasA2 = (p.a2off[cGrp] != 0);

        if (s + 3 < total) issue((s + 3) & 3);   // stage (s+3)&3 != s&3 — no collision
        asm volatile("cp.async.commit_group;\n");

#pragma unroll
        for (int mf = 0; mf < 2; ++mf)
#pragma unroll
            for (int nf = 0; nf < 4; ++nf) {
                const uint32_t* bb = bfr[nf >> 1];
                const int sub = (nf & 1) * 2;
                mma16816(acc[mf][nf], afr[mf], bb[sub], bb[sub + 1]);
            }
#pragma unroll
        for (int mf = 0; mf < 2; ++mf)
#pragma unroll
            for (int nf = 0; nf < 4; ++nf) {
                const uint32_t* bb = b2fr[nf >> 1];
                const int sub = (nf & 1) * 2;
                mma16816(acc[mf][nf], afr[mf], bb[sub], bb[sub + 1]);
            }
        if (hasA2) {
#pragma unroll
            for (int f = 0; f < 2; ++f) ldsm4(afr[f], so + 8192 + aLd[f]);
#pragma unroll
            for (int mf = 0; mf < 2; ++mf)
#pragma unroll
                for (int nf = 0; nf < 4; ++nf) {
                    const uint32_t* bb = bfr[nf >> 1];
                    const int sub = (nf & 1) * 2;
                    mma16816(acc[mf][nf], afr[mf], bb[sub], bb[sub + 1]);
                }
        }

        if (++cKs == segSteps) { cKs = 0; ++cGrp; }
    }

    asm volatile("cp.async.wait_group 0;\n");
    __syncthreads();

    // ---------------- epilogue (per 64-row half; block is 128x64) ----------------
    const float* dgB = p.deg ? (p.deg + (long)b * NN) : nullptr;
    const int* opB = p.outPerm ? (p.outPerm + (long)b * NN) : nullptr;

    if (p.splitOut) {
        // stage hi+lo together: 2 planes x 64 rows x 36 u32 = 18KB
        uint32_t* sH = (uint32_t*)smem;
        uint32_t* sL = sH + 64 * 36;
        for (int h = 0; h < 2; ++h) {
            if ((wm >> 6) == h) {
                const int lrow0 = (wm & 63);
#pragma unroll
                for (int mf = 0; mf < 2; ++mf) {
                    const int rA = lrow0 + mf * 16 + (lane >> 2);   // 0..63 local
                    const int gRow = m0 + h * 64 + rA;
                    const float rs0 = dgB ? (1.0f / dgB[gRow]) : 1.f;
                    const float rs1 = dgB ? (1.0f / dgB[gRow + 8]) : 1.f;
#pragma unroll
                    for (int nf = 0; nf < 4; ++nf) {
                        const int nL = wn + nf * 8 + (lane & 3) * 2;
                        float v[4] = {acc[mf][nf][0] * rs0, acc[mf][nf][1] * rs0,
                                      acc[mf][nf][2] * rs1, acc[mf][nf][3] * rs1};
                        if (p.bias) {
                            const float bz0 = p.bias[n0 + nL], bz1 = p.bias[n0 + nL + 1];
                            v[0] += bz0; v[1] += bz1; v[2] += bz0; v[3] += bz1;
                        }
                        if (p.relu) {
#pragma unroll
                            for (int q = 0; q < 4; ++q) v[q] = fmaxf(v[q], 0.f);
                        }
                        unsigned short oh[4], ol[4];
#pragma unroll
                        for (int q = 0; q < 4; ++q) {
                            const bf16 hi = __float2bfloat16(v[q]);
                            oh[q] = __bfloat16_as_ushort(hi);
                            ol[q] = __bfloat16_as_ushort(
                                __float2bfloat16(v[q] - __bfloat162float(hi)));
                        }
                        const int cu = (nL >> 1);
                        sH[rA * 36 + cu]       = (uint32_t)oh[0] | ((uint32_t)oh[1] << 16);
                        sH[(rA + 8) * 36 + cu] = (uint32_t)oh[2] | ((uint32_t)oh[3] << 16);
                        sL[rA * 36 + cu]       = (uint32_t)ol[0] | ((uint32_t)ol[1] << 16);
                        sL[(rA + 8) * 36 + cu] = (uint32_t)ol[2] | ((uint32_t)ol[3] << 16);
                    }
                }
            }
            __syncthreads();
            {
                // 128 row-plane units x 2 threads; each thread writes 4 uint4
                // -> full 8 uint4 = 64 bf16 per row-plane.  (R15 bug fixed.)
                const int unit = tid >> 1;            // 0..127
                const int r = unit & 63;
                const int pl = unit >> 6;             // 0: hi, 1: lo
                const int q = tid & 1;                // half-row
                const long off = (long)b * p.sC + (long)(m0 + h * 64 + r) * p.ldC + n0;
                bf16* dstB = (pl == 0 ? p.Ch : p.Cl) + off;
                const uint4* srcRow = (const uint4*)((pl == 0 ? sH : sL) + r * 36);
#pragma unroll
                for (int i = 0; i < 4; ++i)
                    ((uint4*)dstB)[q * 4 + i] = srcRow[q * 4 + i];
            }
            __syncthreads();
        }
    } else {
        // fp32 output with row permutation; 64 rows x 68 f32 staging
        float* sF = (float*)smem;
        for (int h = 0; h < 2; ++h) {
            if ((wm >> 6) == h) {
                const int lrow0 = (wm & 63);
#pragma unroll
                for (int mf = 0; mf < 2; ++mf) {
                    const int rA = lrow0 + mf * 16 + (lane >> 2);
#pragma unroll
                    for (int nf = 0; nf < 4; ++nf) {
                        const int nL = wn + nf * 8 + (lane & 3) * 2;
                        float v[4] = {acc[mf][nf][0], acc[mf][nf][1],
                                      acc[mf][nf][2], acc[mf][nf][3]};
                        if (p.bias) {
                            const float bz0 = p.bias[n0 + nL], bz1 = p.bias[n0 + nL + 1];
                            v[0] += bz0; v[1] += bz1; v[2] += bz0; v[3] += bz1;
                        }
                        if (p.relu) {
#pragma unroll
                            for (int q = 0; q < 4; ++q) v[q] = fmaxf(v[q], 0.f);
                        }
                        sF[rA * 68 + nL]           = v[0];
                        sF[rA * 68 + nL + 1]       = v[1];
                        sF[(rA + 8) * 68 + nL]     = v[2];
                        sF[(rA + 8) * 68 + nL + 1] = v[3];
                    }
                }
            }
            __syncthreads();
            {
                // 64 rows x 64 cols fp32; 256 threads: col = tid&63, rows strided by 4
                const int colL = tid & 63;
                const int rb = tid >> 6;          // 0..3
                const int n = n0 + colL;
                if (n < p.Nlim) {
#pragma unroll
                    for (int i = 0; i < 16; ++i) {
                        const int rA = rb + 4 * i;
                        const int row = m0 + h * 64 + rA;
                        const int mo = opB ? opB[row] : row;
                        p.Cf[(long)b * p.sC + (long)mo * p.ldC + n] = sF[rA * 68 + colL];
                    }
                }
            }
            __syncthreads();
        }
    }
}

// ---------------------------------------------------------------------------
extern "C" void kernel_launch(void* const* d_in, const int* in_sizes, int n_in,
                              void* d_out, int out_size)
{
    const float* x4  = (const float*)d_in[0];
    const float* att = (const float*)d_in[1];
    const float* W1  = (const float*)d_in[2];
    const float* b1  = (const float*)d_in[3];
    const float* W2  = (const float*)d_in[4];
    const float* b2  = (const float*)d_in[5];
    float* out = (float*)d_out;

    cudaFuncSetAttribute(mma_gemm, cudaFuncAttributeMaxDynamicSharedMemorySize, SMEM_DYN);

    void *pA, *pDeg, *pPerm, *pAtts, *pXh, *pXl, *pTh, *pTl, *phh, *phl, *pT2h, *pT2l;
    void *pW1h, *pW1l, *pW2h, *pW2l, *pb1p, *pb2p;
    cudaGetSymbolAddress(&pA, g_A);
    cudaGetSymbolAddress(&pDeg, g_deg);
    cudaGetSymbolAddress(&pPerm, g_perm);
    cudaGetSymbolAddress(&pAtts, g_atts);
    cudaGetSymbolAddress(&pXh, g_Xh);  cudaGetSymbolAddress(&pXl, g_Xl);
    cudaGetSymbolAddress(&pTh, g_Th);  cudaGetSymbolAddress(&pTl, g_Tl);
    cudaGetSymbolAddress(&phh, g_hh);  cudaGetSymbolAddress(&phl, g_hl);
    cudaGetSymbolAddress(&pT2h, g_T2h); cudaGetSymbolAddress(&pT2l, g_T2l);
    cudaGetSymbolAddress(&pW1h, g_W1h); cudaGetSymbolAddress(&pW1l, g_W1l);
    cudaGetSymbolAddress(&pW2h, g_W2h); cudaGetSymbolAddress(&pW2l, g_W2l);
    cudaGetSymbolAddress(&pb1p, g_b1p); cudaGetSymbolAddress(&pb2p, g_b2p);

    bf16 *Ab = (bf16*)pA;
    float *deg = (float*)pDeg;
    int *perm = (int*)pPerm;
    float *atts = (float*)pAtts;
    bf16 *Xh = (bf16*)pXh, *Xl = (bf16*)pXl;
    bf16 *Th = (bf16*)pTh, *Tl = (bf16*)pTl;
    bf16 *hh = (bf16*)phh, *hl = (bf16*)phl;
    bf16 *T2h = (bf16*)pT2h, *T2l = (bf16*)pT2l;
    bf16 *W1h = (bf16*)pW1h, *W1l = (bf16*)pW1l;
    bf16 *W2h = (bf16*)pW2h, *W2l = (bf16*)pW2l;
    float *b1p = (float*)pb1p, *b2p = (float*)pb2p;

    // 0: sort (also zeroes deg)
    sort_kernel<<<BB, 512>>>(att);
    // 1: adjacency (band-pruned, symmetric) + degree atomics
    adj_kernel<<<dim3(8, 8, BB), 256>>>(x4, Ab, deg);
    // 2: X split (sorted gather), row-based
    split_kernel<<<dim3(NN, BB), 256>>>(
        x4, Xh, Xl, NN, FF, FFP, (long)NN * FF, (long)NN * FFP, perm);

    // 3: bmm1: T = (1/deg) ⊙ A@(Xh,Xl)  [band-K; B2 = Xl via offset]
    {
        GP p = {};
        p.A[0] = Ab; p.B1[0] = Xh;
        p.b2off = Xl - Xh;
        p.sA[0] = (long)NN * NN; p.sB[0] = (long)NN * FFP;
        p.ngrp = 1; p.steps = NN / 16; p.ldA = NN; p.ldB = FFP;
        p.Ch = Th; p.Cl = Tl; p.sC = (long)NN * FFP; p.ldC = FFP;
        p.deg = deg; p.atts = atts;
        p.bias = nullptr; p.relu = 0; p.Nlim = FFP; p.splitOut = 1;
        mma_gemm<<<dim3(FFP / 64, NN / 128, BB), 256, SMEM_DYN>>>(p);
    }

    // 4: W1 split, row-based
    split_kernel<<<dim3(FFP, 2), 256>>>(
        W1, W1h, W1l, FF, FH, FHPN, (long)FF * FH, (long)FFP * FHPN, nullptr);
    // 5: bias pad
    biaspad_kernel<<<dim3((FHPN + 255) / 256), 256>>>(b1, b2);

    // 6: layer1: super-groups {Xh, W10h, A2=Xl, B2=W10l}, {Th, W11h, A2=Tl, B2=W11l}
    {
        GP p = {};
        const bf16* W10h = W1h;
        const bf16* W11h = W1h + (size_t)FFP * FHPN;
        p.A[0] = Xh; p.B1[0] = W10h; p.a2off[0] = Xl - Xh;
        p.A[1] = Th; p.B1[1] = W11h; p.a2off[1] = Tl - Th;
        p.b2off = W1l - W1h;
        for (int i = 0; i < 2; ++i) { p.sA[i] = (long)NN * FFP; p.sB[i] = 0; }
        p.ngrp = 2; p.steps = FFP / 16; p.ldA = FFP; p.ldB = FHPN;
        p.Ch = hh; p.Cl = hl; p.sC = (long)NN * FHPN; p.ldC = FHPN;
        p.bias = b1p; p.relu = 1; p.Nlim = FHPN; p.splitOut = 1;
        mma_gemm<<<dim3(FHPN / 64, NN / 128, BB), 256, SMEM_DYN>>>(p);
    }

    // 7: bmm2: T2 = (1/deg) ⊙ A@(hh,hl)  [band-K; B2 = hl via offset]
    {
        GP p = {};
        p.A[0] = Ab; p.B1[0] = hh;
        p.b2off = hl - hh;
        p.sA[0] = (long)NN * NN; p.sB[0] = (long)NN * FHPN;
        p.ngrp = 1; p.steps = NN / 16; p.ldA = NN; p.ldB = FHPN;
        p.Ch = T2h; p.Cl = T2l; p.sC = (long)NN * FHPN; p.ldC = FHPN;
        p.deg = deg; p.atts = atts;
        p.bias = nullptr; p.relu = 0; p.Nlim = FHPN; p.splitOut = 1;
        mma_gemm<<<dim3(FHPN / 64, NN / 128, BB), 256, SMEM_DYN>>>(p);
    }

    // 8: W2 split, row-based
    split_kernel<<<dim3(FHPK, 2), 256>>>(
        W2, W2h, W2l, FH, FF, FFP, (long)FH * FF, (long)FHPK * FFP, nullptr);

    // 9: layer2: super-groups {hh, W20h, A2=hl, B2=W20l}, {T2h, W21h, A2=T2l, B2=W21l}
    {
        GP p = {};
        const bf16* W20h = W2h;
        const bf16* W21h = W2h + (size_t)FHPK * FFP;
        p.A[0] = hh;  p.B1[0] = W20h; p.a2off[0] = hl - hh;
        p.A[1] = T2h; p.B1[1] = W21h; p.a2off[1] = T2l - T2h;
        p.b2off = W2l - W2h;
        for (int i = 0; i < 2; ++i) { p.sA[i] = (long)NN * FHPN; p.sB[i] = 0; }
        p.ngrp = 2; p.steps = FHPK / 16; p.ldA = FHPN; p.ldB = FFP;
        p.Cf = out; p.sC = (long)NN * FF; p.ldC = FF;
        p.outPerm = perm;
        p.bias = b2p; p.relu = 1; p.Nlim = FF; p.splitOut = 0;
        mma_gemm<<<dim3(FFP / 64, NN / 128, BB), 256, SMEM_DYN>>>(p);
    }
}